// round 7
// baseline (speedup 1.0000x reference)
#include <cuda_runtime.h>
#include <cuda_fp16.h>
#include <math.h>
#include <stdint.h>

#define NB 8
#define NN 2048
#define ND 128
#define BK 64
#define NIT (NN / BK)   // 32 k-chunks
#define ROWB 160u       // gemm smem row stride bytes (80 halves) -> conflict-free LDS.64
#define ZROWB 288u      // k_z smem row stride bytes (144 halves): 72 mod 32 = 8, same pattern

// ---- scratch (__device__ globals: allocation-guard safe) ----
// fp16, k-pair-permuted within each 16-element block; diag carries +1 self-loop
__device__ __half g_dist[(size_t)NB * NN * NN];   // 67 MB
__device__ float  g_dinv[NB * NN];
__device__ __half g_zT[(size_t)NB * ND * NN];     // [b][d][m], permuted in m
__device__ float  g_mean[NB * ND];
__device__ float  g_rstd[NB * ND];

__device__ __forceinline__ uint32_t smem_u32(const void* p) {
    uint32_t a;
    asm("{ .reg .u64 t; cvta.to.shared.u64 t, %1; cvt.u32.u64 %0, t; }" : "=r"(a) : "l"(p));
    return a;
}

// logical k within 16-block -> physical position (pair permutation so that an
// LDS.64 at 4q yields logical pairs {2q,2q+1} and {2q+8,2q+9})
__device__ __forceinline__ int kperm(int w) {
    return 4 * ((w & 7) >> 1) + ((w >> 3) << 1) + (w & 1);
}

// FMA-only sqrt (avoids MUFU throughput wall on 33.5M sqrts)
__device__ __forceinline__ float fast_sqrt(float x) {
    float xh = 0.5f * x;
    float y = __int_as_float(0x5f3759df - (__float_as_int(x) >> 1));
    y = y * (1.5f - xh * y * y);
    y = y * (1.5f - xh * y * y);
    y = y * (1.5f - xh * y * y);
    return x * y;
}

// ---------------------------------------------------------------------------
// Kernel 1: dist rows (fp16, permuted, +1 diag) + degree -> dinv
// One thread per 16-block: permute in registers, write 2x STG.128.
// grid (NN/2, NB), 256 threads = 2 rows x 128 block-columns.
// ---------------------------------------------------------------------------
__global__ void k_dist(const float* __restrict__ inst) {
    int t = threadIdx.x;
    int half = t >> 7, j = t & 127;
    int n = blockIdx.x * 2 + half, b = blockIdx.y;
    const float2* xb = (const float2*)(inst + (size_t)b * NN * 2);
    float2 xn = xb[n];
    float sqn = xn.x * xn.x + xn.y * xn.y;
    __half* drow = g_dist + (size_t)(b * NN + n) * NN;
    int m0 = j * 16;
    __half out[16];
    float acc = 0.f;
#pragma unroll
    for (int w = 0; w < 16; w++) {
        int m = m0 + w;
        float2 xm = xb[m];
        float sqm = xm.x * xm.x + xm.y * xm.y;
        float dot = xn.x * xm.x + xn.y * xm.y;
        float d2 = sqn + sqm - 2.f * dot;
        float d = (d2 > 0.f) ? fast_sqrt(d2) : 0.f;
        acc += d;
        float v = (m == n) ? d + 1.0f : d;   // fold self-loop into A diagonal
        out[kperm(w)] = __float2half_rn(v);
    }
    *(uint4*)(drow + m0) = ((const uint4*)out)[0];
    *(uint4*)(drow + m0 + 8) = ((const uint4*)out)[1];

    __shared__ float red[256];
    red[t] = acc;
    __syncthreads();
    for (int s = 64; s > 0; s >>= 1) {
        if (j < s) red[half * 128 + j] += red[half * 128 + j + s];
        __syncthreads();
    }
    if (j == 0)
        g_dinv[b * NN + n] = rsqrtf(1.0f + red[half * 128]);
}

// ---------------------------------------------------------------------------
// Kernel 2: h0 = instance @ Wn^T + bn
// ---------------------------------------------------------------------------
__global__ void k_proj(const float* __restrict__ inst, const float* __restrict__ Wn,
                       const float* __restrict__ bn, float* __restrict__ h) {
    int idx = blockIdx.x * 256 + threadIdx.x;
    int d = idx & (ND - 1);
    int row = idx >> 7;
    float2 x = ((const float2*)inst)[row];
    h[idx] = x.x * Wn[2 * d] + x.y * Wn[2 * d + 1] + bn[d];
}

// ---------------------------------------------------------------------------
// Kernel 3 (fp16 MMA): zT[b][e][m] = dinv[m] * sum_d h[m,d] * Wg[e,d]
// A = h tile [128 m x 128 d], B = Wg [128 e x 128 d]; both fp16-converted and
// d-pair-permuted into 288B-row smem. 8 warps, warp tile 64x32, 8 k-steps.
// Output fp16 with m-permutation applied per element.
// ---------------------------------------------------------------------------
__global__ void __launch_bounds__(256) k_z(const float* __restrict__ h,
                                           const float* __restrict__ Wg) {
    extern __shared__ char smc[];
    uint32_t sbase = smem_u32(smc);
    uint32_t as_ = sbase, bs_ = sbase + 128u * ZROWB;
    int t = threadIdx.x, l = t & 31, wid = t >> 5;
    int wm = wid & 1, wn = wid >> 1;
    int row0 = blockIdx.x * 128;   // global row over NB*NN
    int b = row0 >> 11;
    int m0g = row0 & (NN - 1);

    // stage both tiles (convert fp32 -> fp16 with d-pair permutation)
#pragma unroll
    for (int q = 0; q < 16; q++) {
        int idx = q * 256 + t;
        int r = idx >> 5, u = idx & 31;     // u: float4 index over d
        float4 v = *(const float4*)&h[(size_t)(row0 + r) * ND + 4 * u];
        float4 w4 = *(const float4*)&Wg[r * ND + 4 * u];
        int blk = u >> 2;
        int p0 = 2 * (u & 3), p1 = p0 + 1;  // logical pairs in 16-block
        int s0 = (p0 < 4) ? 2 * p0 : 2 * (p0 - 4) + 1;
        int s1 = (p1 < 4) ? 2 * p1 : 2 * (p1 - 4) + 1;
        uint32_t base = (uint32_t)(r * ZROWB + blk * 32);
        *(__half2*)(smc + base + s0 * 4) = __floats2half2_rn(v.x, v.y);
        *(__half2*)(smc + base + s1 * 4) = __floats2half2_rn(v.z, v.w);
        *(__half2*)(smc + 128u * ZROWB + base + s0 * 4) = __floats2half2_rn(w4.x, w4.y);
        *(__half2*)(smc + 128u * ZROWB + base + s1 * 4) = __floats2half2_rn(w4.z, w4.w);
    }
    __syncthreads();

    float c[4][4][4];
#pragma unroll
    for (int i = 0; i < 4; i++)
#pragma unroll
        for (int j = 0; j < 4; j++)
#pragma unroll
            for (int k = 0; k < 4; k++) c[i][j][k] = 0.f;

#pragma unroll
    for (int s = 0; s < 8; s++) {
        uint32_t bf[4][2];
#pragma unroll
        for (int nt = 0; nt < 4; nt++) {
            int nrow = wn * 32 + nt * 8 + (l >> 2);
            asm volatile("ld.shared.v2.b32 {%0,%1}, [%2];"
                         : "=r"(bf[nt][0]), "=r"(bf[nt][1])
                         : "r"(bs_ + (uint32_t)(nrow * ZROWB + s * 32 + (l & 3) * 8)));
        }
#pragma unroll
        for (int mt = 0; mt < 4; mt++) {
            uint32_t af[4];
            int mrow = wm * 64 + mt * 16 + (l >> 2);
            asm volatile("ld.shared.v2.b32 {%0,%1}, [%2];"
                         : "=r"(af[0]), "=r"(af[2])
                         : "r"(as_ + (uint32_t)(mrow * ZROWB + s * 32 + (l & 3) * 8)));
            asm volatile("ld.shared.v2.b32 {%0,%1}, [%2];"
                         : "=r"(af[1]), "=r"(af[3])
                         : "r"(as_ + (uint32_t)((mrow + 8) * ZROWB + s * 32 + (l & 3) * 8)));
#pragma unroll
            for (int nt = 0; nt < 4; nt++) {
                asm volatile(
                    "mma.sync.aligned.m16n8k16.row.col.f32.f16.f16.f32 "
                    "{%0,%1,%2,%3}, {%4,%5,%6,%7}, {%8,%9}, {%0,%1,%2,%3};"
                    : "+f"(c[mt][nt][0]), "+f"(c[mt][nt][1]),
                      "+f"(c[mt][nt][2]), "+f"(c[mt][nt][3])
                    : "r"(af[0]), "r"(af[1]), "r"(af[2]), "r"(af[3]),
                      "r"(bf[nt][0]), "r"(bf[nt][1]));
            }
        }
    }

    // epilogue: apply dinv, write zT[e][m] fp16 with m-permutation
    __half* zTb = g_zT + (size_t)b * ND * NN;
    int wloc = l >> 2;
    int ph0 = 4 * (wloc >> 1) + (wloc & 1);   // phys index of r0 in 16-block; r1 -> +2
#pragma unroll
    for (int mt = 0; mt < 4; mt++) {
        int mblk = wm * 64 + mt * 16;
        int r0 = mblk + wloc, r1 = r0 + 8;
        float dv0 = g_dinv[b * NN + m0g + r0];
        float dv1 = g_dinv[b * NN + m0g + r1];
        int pb = m0g + mblk + ph0;
#pragma unroll
        for (int nt = 0; nt < 4; nt++) {
            int cc = wn * 32 + nt * 8 + 2 * (l & 3);
            zTb[(size_t)cc * NN + pb]           = __float2half_rn(c[mt][nt][0] * dv0);
            zTb[(size_t)(cc + 1) * NN + pb]     = __float2half_rn(c[mt][nt][1] * dv0);
            zTb[(size_t)cc * NN + pb + 2]       = __float2half_rn(c[mt][nt][2] * dv1);
            zTb[(size_t)(cc + 1) * NN + pb + 2] = __float2half_rn(c[mt][nt][3] * dv1);
        }
    }
}

// ---------------------------------------------------------------------------
// Kernel 4: fp16 m16n8k16 mma.sync GEMM (unchanged from R6 winner).
// h[n,:] = tanh( dinv[n]*((dist+I)[n,:] @ z) + bg ) + h[n,:]
// ---------------------------------------------------------------------------
__global__ void __launch_bounds__(256) k_gemm_mma(float* __restrict__ h,
                                                  const float* __restrict__ bg_l) {
    extern __shared__ char smc[];
    uint32_t sbase = smem_u32(smc);
    int t = threadIdx.x, l = t & 31, wid = t >> 5;
    int wm = wid & 1, wn = wid >> 1;
    int b = blockIdx.y, n0 = blockIdx.x * 128;
    const __half* Ab = g_dist + ((size_t)b * NN + n0) * NN;
    const __half* Bt = g_zT + (size_t)b * ND * NN;

    float c[4][4][4];
#pragma unroll
    for (int i = 0; i < 4; i++)
#pragma unroll
        for (int j = 0; j < 4; j++)
#pragma unroll
            for (int k = 0; k < 4; k++) c[i][j][k] = 0.f;

#define LOADT(P, K0)                                                             \
    {                                                                            \
        uint32_t as_ = sbase + (P) * 40960u;                                     \
        uint32_t bs_ = as_ + 20480u;                                             \
        _Pragma("unroll")                                                        \
        for (int q = 0; q < 4; q++) {                                            \
            int idx = q * 256 + t;                                               \
            int r_ = idx >> 3;                                                   \
            int c16 = idx & 7;                                                   \
            uint32_t so = (uint32_t)(r_ * ROWB + c16 * 16);                      \
            asm volatile("cp.async.cg.shared.global [%0], [%1], 16;"             \
                         :: "r"(as_ + so), "l"(Ab + (size_t)r_ * NN + (K0) + c16 * 8)); \
            asm volatile("cp.async.cg.shared.global [%0], [%1], 16;"             \
                         :: "r"(bs_ + so), "l"(Bt + (size_t)r_ * NN + (K0) + c16 * 8)); \
        }                                                                        \
        asm volatile("cp.async.commit_group;");                                  \
    }

#define COMPUTE(P)                                                               \
    {                                                                            \
        uint32_t as_ = sbase + (P) * 40960u;                                     \
        uint32_t bs_ = as_ + 20480u;                                             \
        _Pragma("unroll")                                                        \
        for (int s = 0; s < 4; s++) {                                            \
            uint32_t bf[4][2];                                                   \
            _Pragma("unroll")                                                    \
            for (int nt = 0; nt < 4; nt++) {                                     \
                int nrow = wn * 32 + nt * 8 + (l >> 2);                          \
                asm volatile("ld.shared.v2.b32 {%0,%1}, [%2];"                   \
                             : "=r"(bf[nt][0]), "=r"(bf[nt][1])                  \
                             : "r"(bs_ + (uint32_t)(nrow * ROWB + s * 32 + (l & 3) * 8))); \
            }                                                                    \
            _Pragma("unroll")                                                    \
            for (int mt = 0; mt < 4; mt++) {                                     \
                uint32_t af[4];                                                  \
                int mrow = wm * 64 + mt * 16 + (l >> 2);                         \
                asm volatile("ld.shared.v2.b32 {%0,%1}, [%2];"                   \
                             : "=r"(af[0]), "=r"(af[2])                          \
                             : "r"(as_ + (uint32_t)(mrow * ROWB + s * 32 + (l & 3) * 8))); \
                asm volatile("ld.shared.v2.b32 {%0,%1}, [%2];"                   \
                             : "=r"(af[1]), "=r"(af[3])                          \
                             : "r"(as_ + (uint32_t)((mrow + 8) * ROWB + s * 32 + (l & 3) * 8))); \
                _Pragma("unroll")                                                \
                for (int nt = 0; nt < 4; nt++) {                                 \
                    asm volatile(                                                \
                        "mma.sync.aligned.m16n8k16.row.col.f32.f16.f16.f32 "     \
                        "{%0,%1,%2,%3}, {%4,%5,%6,%7}, {%8,%9}, {%0,%1,%2,%3};"  \
                        : "+f"(c[mt][nt][0]), "+f"(c[mt][nt][1]),                \
                          "+f"(c[mt][nt][2]), "+f"(c[mt][nt][3])                 \
                        : "r"(af[0]), "r"(af[1]), "r"(af[2]), "r"(af[3]),        \
                          "r"(bf[nt][0]), "r"(bf[nt][1]));                       \
                }                                                                \
            }                                                                    \
        }                                                                        \
    }

    LOADT(0, 0);
    LOADT(1, BK);
    int p = 0;
    for (int it = 0; it < NIT; it++) {
        if (it + 1 < NIT)
            asm volatile("cp.async.wait_group 1;");
        else
            asm volatile("cp.async.wait_group 0;");
        __syncthreads();
        if (it + 2 < NIT) {
            int pn = (it + 2) % 3;
            LOADT(pn, (it + 2) * BK);
        }
        COMPUTE(p);
        p = (p + 1) % 3;
    }

#pragma unroll
    for (int mt = 0; mt < 4; mt++) {
        int r0 = n0 + wm * 64 + mt * 16 + (l >> 2);
        int r1 = r0 + 8;
        float dv0 = g_dinv[b * NN + r0];
        float dv1 = g_dinv[b * NN + r1];
#pragma unroll
        for (int nt = 0; nt < 4; nt++) {
            int cc = wn * 32 + nt * 8 + 2 * (l & 3);
            float bg0 = bg_l[cc], bg1 = bg_l[cc + 1];
            size_t h0o = ((size_t)b * NN + r0) * ND + cc;
            size_t h1o = ((size_t)b * NN + r1) * ND + cc;
            float2 hv0 = *(const float2*)&h[h0o];
            float2 hv1 = *(const float2*)&h[h1o];
            float2 o0, o1;
            o0.x = tanhf(dv0 * c[mt][nt][0] + bg0) + hv0.x;
            o0.y = tanhf(dv0 * c[mt][nt][1] + bg1) + hv0.y;
            o1.x = tanhf(dv1 * c[mt][nt][2] + bg0) + hv1.x;
            o1.y = tanhf(dv1 * c[mt][nt][3] + bg1) + hv1.y;
            *(float2*)&h[h0o] = o0;
            *(float2*)&h[h1o] = o1;
        }
    }
#undef LOADT
#undef COMPUTE
}

// ---------------------------------------------------------------------------
// Kernel 5: GraphNorm stats per (b, d)
// ---------------------------------------------------------------------------
__global__ void k_stats(const float* __restrict__ h, const float* __restrict__ gna) {
    int b = blockIdx.y;
    int d0 = blockIdx.x * 8;
    int t = threadIdx.x;
    int dc = t & 7, r = t >> 3;
    const float* hb = h + (size_t)b * NN * ND;
    float s = 0.f, q = 0.f;
    for (int k = 0; k < NN; k += 32) {
        float v = hb[(size_t)(k + r) * ND + d0 + dc];
        s += v;
        q = fmaf(v, v, q);
    }
    __shared__ float ss[32][8], sq[32][8];
    ss[r][dc] = s; sq[r][dc] = q;
    __syncthreads();
    for (int off = 16; off > 0; off >>= 1) {
        if (r < off) {
            ss[r][dc] += ss[r + off][dc];
            sq[r][dc] += sq[r + off][dc];
        }
        __syncthreads();
    }
    if (t < 8) {
        float mean = ss[0][t] * (1.f / NN);
        float eh2 = sq[0][t] * (1.f / NN);
        float a = gna[d0 + t];
        float var = eh2 - (2.f * a - a * a) * mean * mean;
        g_mean[b * ND + d0 + t] = mean;
        g_rstd[b * ND + d0 + t] = rsqrtf(var + 1e-5f);
    }
}

// ---------------------------------------------------------------------------
// Kernel 6: normalize in place
// ---------------------------------------------------------------------------
__global__ void k_norm(float* __restrict__ h, const float* __restrict__ gnw,
                       const float* __restrict__ gnb, const float* __restrict__ gna) {
    int idx = blockIdx.x * 256 + threadIdx.x;
    int d = idx & (ND - 1);
    int b = idx >> 18;
    float m = g_mean[b * ND + d];
    float rs = g_rstd[b * ND + d];
    float v = h[idx];
    h[idx] = gnw[d] * (v - gna[d] * m) * rs + gnb[d];
}

// ---------------------------------------------------------------------------
extern "C" void kernel_launch(void* const* d_in, const int* in_sizes, int n_in,
                              void* d_out, int out_size) {
    const float* inst = (const float*)d_in[0];
    const float* Wn   = (const float*)d_in[1];
    const float* bn   = (const float*)d_in[2];
    const float* Wg   = (const float*)d_in[3];
    const float* bg   = (const float*)d_in[4];
    const float* gnw  = (const float*)d_in[5];
    const float* gnb  = (const float*)d_in[6];
    const float* gna  = (const float*)d_in[7];
    float* h = (float*)d_out;

    const int SMEM_GEMM = 3 * 40960;          // 3 stages x (A 20KB + B 20KB)
    const int SMEM_Z    = 2 * 128 * (int)ZROWB;  // 72 KB
    static int smem_set = 0;
    if (!smem_set) {
        cudaFuncSetAttribute(k_gemm_mma, cudaFuncAttributeMaxDynamicSharedMemorySize, SMEM_GEMM);
        cudaFuncSetAttribute(k_z, cudaFuncAttributeMaxDynamicSharedMemorySize, SMEM_Z);
        smem_set = 1;
    }

    k_dist<<<dim3(NN / 2, NB), 256>>>(inst);
    k_proj<<<(NB * NN * ND) / 256, 256>>>(inst, Wn, bn, h);
    for (int l = 0; l < 3; l++) {
        k_z<<<NB * NN / 128, 256, SMEM_Z>>>(h, Wg + l * ND * ND);
        k_gemm_mma<<<dim3(NN / 128, NB), 256, SMEM_GEMM>>>(h, bg + l * ND);
        k_stats<<<dim3(ND / 8, NB), 256>>>(h, gna);
        k_norm<<<(NB * NN * ND) / 256, 256>>>(h, gnw, gnb, gna);
    }
}

// round 8
// speedup vs baseline: 1.0057x; 1.0057x over previous
#include <cuda_runtime.h>
#include <cuda_fp16.h>
#include <math.h>
#include <stdint.h>

#define NB 8
#define NN 2048
#define ND 128
#define BK 64
#define NIT (NN / BK)   // 32 k-chunks
#define ROWB 160u       // gemm smem row stride bytes (80 halves) -> conflict-free LDS.64
#define ZROWB 288u      // k_z smem row stride bytes: 72 mod 32 = 8, conflict-free pattern

// ---- scratch (__device__ globals: allocation-guard safe) ----
// fp16, k-pair-permuted within each 16-element block; diag carries +1 self-loop
__device__ __half g_dist[(size_t)NB * NN * NN];   // 67 MB
__device__ float  g_dinv[NB * NN];
__device__ __half g_zT[(size_t)NB * ND * NN];     // [b][d][m], permuted in m
__device__ float  g_mean[NB * ND];
__device__ float  g_rstd[NB * ND];

__device__ __forceinline__ uint32_t smem_u32(const void* p) {
    uint32_t a;
    asm("{ .reg .u64 t; cvta.to.shared.u64 t, %1; cvt.u32.u64 %0, t; }" : "=r"(a) : "l"(p));
    return a;
}

// logical k within 16-block -> physical position (pair permutation so that an
// LDS.64 at 4q yields logical pairs {2q,2q+1} and {2q+8,2q+9})
__device__ __forceinline__ int kperm(int w) {
    return 4 * ((w & 7) >> 1) + ((w >> 3) << 1) + (w & 1);
}

// FMA-only sqrt (avoids MUFU throughput wall on 33.5M sqrts)
__device__ __forceinline__ float fast_sqrt(float x) {
    float xh = 0.5f * x;
    float y = __int_as_float(0x5f3759df - (__float_as_int(x) >> 1));
    y = y * (1.5f - xh * y * y);
    y = y * (1.5f - xh * y * y);
    y = y * (1.5f - xh * y * y);
    return x * y;
}

// ---------------------------------------------------------------------------
// Kernel 1: dist rows (fp16, permuted, +1 diag) + degree -> dinv
// One thread per 16-block: permute in registers, write 2x STG.128.
// ---------------------------------------------------------------------------
__global__ void k_dist(const float* __restrict__ inst) {
    int t = threadIdx.x;
    int half = t >> 7, j = t & 127;
    int n = blockIdx.x * 2 + half, b = blockIdx.y;
    const float2* xb = (const float2*)(inst + (size_t)b * NN * 2);
    float2 xn = xb[n];
    float sqn = xn.x * xn.x + xn.y * xn.y;
    __half* drow = g_dist + (size_t)(b * NN + n) * NN;
    int m0 = j * 16;
    __half out[16];
    float acc = 0.f;
#pragma unroll
    for (int w = 0; w < 16; w++) {
        int m = m0 + w;
        float2 xm = xb[m];
        float sqm = xm.x * xm.x + xm.y * xm.y;
        float dot = xn.x * xm.x + xn.y * xm.y;
        float d2 = sqn + sqm - 2.f * dot;
        float d = (d2 > 0.f) ? fast_sqrt(d2) : 0.f;
        acc += d;
        float v = (m == n) ? d + 1.0f : d;   // fold self-loop into A diagonal
        out[kperm(w)] = __float2half_rn(v);
    }
    *(uint4*)(drow + m0) = ((const uint4*)out)[0];
    *(uint4*)(drow + m0 + 8) = ((const uint4*)out)[1];

    __shared__ float red[256];
    red[t] = acc;
    __syncthreads();
    for (int s = 64; s > 0; s >>= 1) {
        if (j < s) red[half * 128 + j] += red[half * 128 + j + s];
        __syncthreads();
    }
    if (j == 0)
        g_dinv[b * NN + n] = rsqrtf(1.0f + red[half * 128]);
}

// ---------------------------------------------------------------------------
// Kernel 2: h0 = instance @ Wn^T + bn
// ---------------------------------------------------------------------------
__global__ void k_proj(const float* __restrict__ inst, const float* __restrict__ Wn,
                       const float* __restrict__ bn, float* __restrict__ h) {
    int idx = blockIdx.x * 256 + threadIdx.x;
    int d = idx & (ND - 1);
    int row = idx >> 7;
    float2 x = ((const float2*)inst)[row];
    h[idx] = x.x * Wn[2 * d] + x.y * Wn[2 * d + 1] + bn[d];
}

// ---------------------------------------------------------------------------
// Kernel 3 (fp16 MMA, output-major orientation):
//   zT[b][e][m] = dinv[m] * sum_d Wg[e,d] * h[m,d]
// A = Wg (rows=e), B = h tile (rows=m) -> MMA output rows = e = zT major dim.
// Result staged in smem (reusing A region), dinv applied, then coalesced
// STG.128 stores of m-contiguous runs. m-permutation applied at the STS.
// ---------------------------------------------------------------------------
__global__ void __launch_bounds__(256) k_z(const float* __restrict__ h,
                                           const float* __restrict__ Wg) {
    extern __shared__ char smc[];
    uint32_t sbase = smem_u32(smc);
    uint32_t as_ = sbase, bs_ = sbase + 128u * ZROWB;   // A=Wg, B=h
    int t = threadIdx.x, l = t & 31, wid = t >> 5;
    int wm = wid & 1, wn = wid >> 1;   // wm: e-half (64), wn: m-quarter (32)
    int row0 = blockIdx.x * 128;       // global row over NB*NN (m dimension)
    int b = row0 >> 11;
    int m0g = row0 & (NN - 1);

    // stage tiles (fp32 -> fp16 with d-pair permutation)
#pragma unroll
    for (int q = 0; q < 16; q++) {
        int idx = q * 256 + t;
        int r = idx >> 5, u = idx & 31;     // u: float4 index over d
        float4 wv = *(const float4*)&Wg[r * ND + 4 * u];
        float4 hv = *(const float4*)&h[(size_t)(row0 + r) * ND + 4 * u];
        int blk = u >> 2;
        int p0 = 2 * (u & 3), p1 = p0 + 1;  // logical pair indices in 16-block
        int s0 = (p0 < 4) ? 2 * p0 : 2 * (p0 - 4) + 1;  // physical pair slots
        int s1 = (p1 < 4) ? 2 * p1 : 2 * (p1 - 4) + 1;
        uint32_t base = (uint32_t)(r * ZROWB + blk * 32);
        *(__half2*)(smc + base + s0 * 4) = __floats2half2_rn(wv.x, wv.y);
        *(__half2*)(smc + base + s1 * 4) = __floats2half2_rn(wv.z, wv.w);
        *(__half2*)(smc + 128u * ZROWB + base + s0 * 4) = __floats2half2_rn(hv.x, hv.y);
        *(__half2*)(smc + 128u * ZROWB + base + s1 * 4) = __floats2half2_rn(hv.z, hv.w);
    }
    __syncthreads();

    float c[4][4][4];
#pragma unroll
    for (int i = 0; i < 4; i++)
#pragma unroll
        for (int j = 0; j < 4; j++)
#pragma unroll
            for (int k = 0; k < 4; k++) c[i][j][k] = 0.f;

#pragma unroll
    for (int s = 0; s < 8; s++) {
        uint32_t bf[4][2];
#pragma unroll
        for (int nt = 0; nt < 4; nt++) {
            int nrow = wn * 32 + nt * 8 + (l >> 2);   // m rows
            asm volatile("ld.shared.v2.b32 {%0,%1}, [%2];"
                         : "=r"(bf[nt][0]), "=r"(bf[nt][1])
                         : "r"(bs_ + (uint32_t)(nrow * ZROWB + s * 32 + (l & 3) * 8)));
        }
#pragma unroll
        for (int mt = 0; mt < 4; mt++) {
            uint32_t af[4];
            int mrow = wm * 64 + mt * 16 + (l >> 2);  // e rows
            asm volatile("ld.shared.v2.b32 {%0,%1}, [%2];"
                         : "=r"(af[0]), "=r"(af[2])
                         : "r"(as_ + (uint32_t)(mrow * ZROWB + s * 32 + (l & 3) * 8)));
            asm volatile("ld.shared.v2.b32 {%0,%1}, [%2];"
                         : "=r"(af[1]), "=r"(af[3])
                         : "r"(as_ + (uint32_t)((mrow + 8) * ZROWB + s * 32 + (l & 3) * 8)));
#pragma unroll
            for (int nt = 0; nt < 4; nt++) {
                asm volatile(
                    "mma.sync.aligned.m16n8k16.row.col.f32.f16.f16.f32 "
                    "{%0,%1,%2,%3}, {%4,%5,%6,%7}, {%8,%9}, {%0,%1,%2,%3};"
                    : "+f"(c[mt][nt][0]), "+f"(c[mt][nt][1]),
                      "+f"(c[mt][nt][2]), "+f"(c[mt][nt][3])
                    : "r"(af[0]), "r"(af[1]), "r"(af[2]), "r"(af[3]),
                      "r"(bf[nt][0]), "r"(bf[nt][1]));
            }
        }
    }

    // dinv per (nt): logical m pair at wn*32 + nt*8 + 2*(l&3)
    float2 dv[4];
#pragma unroll
    for (int nt = 0; nt < 4; nt++)
        dv[nt] = *(const float2*)&g_dinv[b * NN + m0g + wn * 32 + nt * 8 + 2 * (l & 3)];

    __syncthreads();  // A region reads complete everywhere; reuse as zbuf
    // zbuf[e][m_phys], 288B rows. c values: rows e0/e0+8, cols (m, m+1).
#pragma unroll
    for (int mt = 0; mt < 4; mt++) {
        int e0 = wm * 64 + mt * 16 + (l >> 2);
#pragma unroll
        for (int nt = 0; nt < 4; nt++) {
            int mloc = wn * 32 + nt * 8 + 2 * (l & 3);
            int phys = (mloc & ~15) + kperm(mloc & 15);   // pair-adjacent
            *(__half2*)(smc + (uint32_t)(e0 * ZROWB + phys * 2)) =
                __floats2half2_rn(c[mt][nt][0] * dv[nt].x, c[mt][nt][1] * dv[nt].y);
            *(__half2*)(smc + (uint32_t)((e0 + 8) * ZROWB + phys * 2)) =
                __floats2half2_rn(c[mt][nt][2] * dv[nt].x, c[mt][nt][3] * dv[nt].y);
        }
    }
    __syncthreads();

    // coalesced copy-out: 128 e-rows x 128 m-halves (256B per row)
    __half* zTb = g_zT + (size_t)b * ND * NN;
#pragma unroll
    for (int it = 0; it < 8; it++) {
        int idx = it * 256 + t;
        int e = idx >> 4, ch = idx & 15;
        uint4 v = *(const uint4*)(smc + (uint32_t)(e * ZROWB + ch * 16));
        *(uint4*)(zTb + (size_t)e * NN + m0g + ch * 8) = v;
    }
}

// ---------------------------------------------------------------------------
// Kernel 4: fp16 m16n8k16 mma.sync GEMM with per-s fragment double-buffering.
// h[n,:] = tanh( dinv[n]*((dist+I)[n,:] @ z) + bg ) + h[n,:]
// ---------------------------------------------------------------------------
__global__ void __launch_bounds__(256) k_gemm_mma(float* __restrict__ h,
                                                  const float* __restrict__ bg_l) {
    extern __shared__ char smc[];
    uint32_t sbase = smem_u32(smc);
    int t = threadIdx.x, l = t & 31, wid = t >> 5;
    int wm = wid & 1, wn = wid >> 1;
    int b = blockIdx.y, n0 = blockIdx.x * 128;
    const __half* Ab = g_dist + ((size_t)b * NN + n0) * NN;
    const __half* Bt = g_zT + (size_t)b * ND * NN;

    float c[4][4][4];
#pragma unroll
    for (int i = 0; i < 4; i++)
#pragma unroll
        for (int j = 0; j < 4; j++)
#pragma unroll
            for (int k = 0; k < 4; k++) c[i][j][k] = 0.f;

    uint32_t af[2][4][4], bf[2][4][2];   // double-buffered fragments

#define LOADT(P, K0)                                                             \
    {                                                                            \
        uint32_t xas = sbase + (P) * 40960u;                                     \
        uint32_t xbs = xas + 20480u;                                             \
        _Pragma("unroll")                                                        \
        for (int q = 0; q < 4; q++) {                                            \
            int idx = q * 256 + t;                                               \
            int r_ = idx >> 3;                                                   \
            int c16 = idx & 7;                                                   \
            uint32_t so = (uint32_t)(r_ * ROWB + c16 * 16);                      \
            asm volatile("cp.async.cg.shared.global [%0], [%1], 16;"             \
                         :: "r"(xas + so), "l"(Ab + (size_t)r_ * NN + (K0) + c16 * 8)); \
            asm volatile("cp.async.cg.shared.global [%0], [%1], 16;"             \
                         :: "r"(xbs + so), "l"(Bt + (size_t)r_ * NN + (K0) + c16 * 8)); \
        }                                                                        \
        asm volatile("cp.async.commit_group;");                                  \
    }

#define LDFRAG(AS, BS, BUF, S)                                                   \
    {                                                                            \
        _Pragma("unroll")                                                        \
        for (int nt = 0; nt < 4; nt++) {                                         \
            int nrow = wn * 32 + nt * 8 + (l >> 2);                              \
            asm volatile("ld.shared.v2.b32 {%0,%1}, [%2];"                       \
                         : "=r"(bf[BUF][nt][0]), "=r"(bf[BUF][nt][1])            \
                         : "r"((BS) + (uint32_t)(nrow * ROWB + (S) * 32 + (l & 3) * 8))); \
        }                                                                        \
        _Pragma("unroll")                                                        \
        for (int mt = 0; mt < 4; mt++) {                                         \
            int mrow = wm * 64 + mt * 16 + (l >> 2);                             \
            asm volatile("ld.shared.v2.b32 {%0,%1}, [%2];"                       \
                         : "=r"(af[BUF][mt][0]), "=r"(af[BUF][mt][2])            \
                         : "r"((AS) + (uint32_t)(mrow * ROWB + (S) * 32 + (l & 3) * 8))); \
            asm volatile("ld.shared.v2.b32 {%0,%1}, [%2];"                       \
                         : "=r"(af[BUF][mt][1]), "=r"(af[BUF][mt][3])            \
                         : "r"((AS) + (uint32_t)((mrow + 8) * ROWB + (S) * 32 + (l & 3) * 8))); \
        }                                                                        \
    }

#define DOMMA(BUF)                                                               \
    {                                                                            \
        _Pragma("unroll")                                                        \
        for (int mt = 0; mt < 4; mt++)                                           \
            _Pragma("unroll")                                                    \
            for (int nt = 0; nt < 4; nt++) {                                     \
                asm volatile(                                                    \
                    "mma.sync.aligned.m16n8k16.row.col.f32.f16.f16.f32 "         \
                    "{%0,%1,%2,%3}, {%4,%5,%6,%7}, {%8,%9}, {%0,%1,%2,%3};"      \
                    : "+f"(c[mt][nt][0]), "+f"(c[mt][nt][1]),                    \
                      "+f"(c[mt][nt][2]), "+f"(c[mt][nt][3])                     \
                    : "r"(af[BUF][mt][0]), "r"(af[BUF][mt][1]),                  \
                      "r"(af[BUF][mt][2]), "r"(af[BUF][mt][3]),                  \
                      "r"(bf[BUF][nt][0]), "r"(bf[BUF][nt][1]));                 \
            }                                                                    \
    }

    LOADT(0, 0);
    LOADT(1, BK);
    int p = 0;
    for (int it = 0; it < NIT; it++) {
        if (it + 1 < NIT)
            asm volatile("cp.async.wait_group 1;");
        else
            asm volatile("cp.async.wait_group 0;");
        __syncthreads();
        if (it + 2 < NIT) {
            int pn = (it + 2) % 3;
            LOADT(pn, (it + 2) * BK);
        }
        uint32_t as_ = sbase + p * 40960u;
        uint32_t bs_ = as_ + 20480u;
        LDFRAG(as_, bs_, 0, 0);
#pragma unroll
        for (int s = 0; s < 4; s++) {
            if (s < 3) LDFRAG(as_, bs_, (s + 1) & 1, s + 1);
            DOMMA(s & 1);
        }
        p = (p + 1) % 3;
    }

    // epilogue: dinv + bias + tanh + residual (self-loop already in A diag)
#pragma unroll
    for (int mt = 0; mt < 4; mt++) {
        int r0 = n0 + wm * 64 + mt * 16 + (l >> 2);
        int r1 = r0 + 8;
        float dv0 = g_dinv[b * NN + r0];
        float dv1 = g_dinv[b * NN + r1];
#pragma unroll
        for (int nt = 0; nt < 4; nt++) {
            int cc = wn * 32 + nt * 8 + 2 * (l & 3);
            float bg0 = bg_l[cc], bg1 = bg_l[cc + 1];
            size_t h0o = ((size_t)b * NN + r0) * ND + cc;
            size_t h1o = ((size_t)b * NN + r1) * ND + cc;
            float2 hv0 = *(const float2*)&h[h0o];
            float2 hv1 = *(const float2*)&h[h1o];
            float2 o0, o1;
            o0.x = tanhf(dv0 * c[mt][nt][0] + bg0) + hv0.x;
            o0.y = tanhf(dv0 * c[mt][nt][1] + bg1) + hv0.y;
            o1.x = tanhf(dv1 * c[mt][nt][2] + bg0) + hv1.x;
            o1.y = tanhf(dv1 * c[mt][nt][3] + bg1) + hv1.y;
            *(float2*)&h[h0o] = o0;
            *(float2*)&h[h1o] = o1;
        }
    }
#undef LOADT
#undef LDFRAG
#undef DOMMA
}

// ---------------------------------------------------------------------------
// Kernel 5: GraphNorm stats per (b, d)
// ---------------------------------------------------------------------------
__global__ void k_stats(const float* __restrict__ h, const float* __restrict__ gna) {
    int b = blockIdx.y;
    int d0 = blockIdx.x * 8;
    int t = threadIdx.x;
    int dc = t & 7, r = t >> 3;
    const float* hb = h + (size_t)b * NN * ND;
    float s = 0.f, q = 0.f;
    for (int k = 0; k < NN; k += 32) {
        float v = hb[(size_t)(k + r) * ND + d0 + dc];
        s += v;
        q = fmaf(v, v, q);
    }
    __shared__ float ss[32][8], sq[32][8];
    ss[r][dc] = s; sq[r][dc] = q;
    __syncthreads();
    for (int off = 16; off > 0; off >>= 1) {
        if (r < off) {
            ss[r][dc] += ss[r + off][dc];
            sq[r][dc] += sq[r + off][dc];
        }
        __syncthreads();
    }
    if (t < 8) {
        float mean = ss[0][t] * (1.f / NN);
        float eh2 = sq[0][t] * (1.f / NN);
        float a = gna[d0 + t];
        float var = eh2 - (2.f * a - a * a) * mean * mean;
        g_mean[b * ND + d0 + t] = mean;
        g_rstd[b * ND + d0 + t] = rsqrtf(var + 1e-5f);
    }
}

// ---------------------------------------------------------------------------
// Kernel 6: normalize in place
// ---------------------------------------------------------------------------
__global__ void k_norm(float* __restrict__ h, const float* __restrict__ gnw,
                       const float* __restrict__ gnb, const float* __restrict__ gna) {
    int idx = blockIdx.x * 256 + threadIdx.x;
    int d = idx & (ND - 1);
    int b = idx >> 18;
    float m = g_mean[b * ND + d];
    float rs = g_rstd[b * ND + d];
    float v = h[idx];
    h[idx] = gnw[d] * (v - gna[d] * m) * rs + gnb[d];
}

// ---------------------------------------------------------------------------
extern "C" void kernel_launch(void* const* d_in, const int* in_sizes, int n_in,
                              void* d_out, int out_size) {
    const float* inst = (const float*)d_in[0];
    const float* Wn   = (const float*)d_in[1];
    const float* bn   = (const float*)d_in[2];
    const float* Wg   = (const float*)d_in[3];
    const float* bg   = (const float*)d_in[4];
    const float* gnw  = (const float*)d_in[5];
    const float* gnb  = (const float*)d_in[6];
    const float* gna  = (const float*)d_in[7];
    float* h = (float*)d_out;

    const int SMEM_GEMM = 3 * 40960;             // 3 stages x (A 20KB + B 20KB)
    const int SMEM_Z    = 2 * 128 * (int)ZROWB;  // 72 KB (A reused as zbuf)
    static int smem_set = 0;
    if (!smem_set) {
        cudaFuncSetAttribute(k_gemm_mma, cudaFuncAttributeMaxDynamicSharedMemorySize, SMEM_GEMM);
        cudaFuncSetAttribute(k_z, cudaFuncAttributeMaxDynamicSharedMemorySize, SMEM_Z);
        smem_set = 1;
    }

    k_dist<<<dim3(NN / 2, NB), 256>>>(inst);
    k_proj<<<(NB * NN * ND) / 256, 256>>>(inst, Wn, bn, h);
    for (int l = 0; l < 3; l++) {
        k_z<<<NB * NN / 128, 256, SMEM_Z>>>(h, Wg + l * ND * ND);
        k_gemm_mma<<<dim3(NN / 128, NB), 256, SMEM_GEMM>>>(h, bg + l * ND);
        k_stats<<<dim3(ND / 8, NB), 256>>>(h, gna);
        k_norm<<<(NB * NN * ND) / 256, 256>>>(h, gnw, gnb, gna);
    }
}

// round 9
// speedup vs baseline: 1.3452x; 1.3376x over previous
#include <cuda_runtime.h>
#include <cuda_fp16.h>
#include <math.h>
#include <stdint.h>

#define NB 8
#define NN 2048
#define ND 128
#define BK 64
#define NIT (NN / BK)   // 32 k-chunks
#define ROWB 160u       // gemm smem row stride bytes (80 halves) -> conflict-free LDS.64
#define ZROWB 288u      // k_z smem row stride bytes: 72 mod 32 = 8, conflict-free pattern

// ---- scratch (__device__ globals: allocation-guard safe) ----
__device__ __half g_dist[(size_t)NB * NN * NN];   // 67 MB, k-pair-permuted, diag has +1
__device__ float  g_dinv[NB * NN];
__device__ __half g_zT[(size_t)NB * ND * NN];     // [b][d][m], permuted in m
__device__ float  g_mean[NB * ND];
__device__ float  g_rstd[NB * ND];
__device__ float2 g_part[NB * 16 * ND];           // per-(b, n-tile) stats partials

__device__ __forceinline__ uint32_t smem_u32(const void* p) {
    uint32_t a;
    asm("{ .reg .u64 t; cvta.to.shared.u64 t, %1; cvt.u32.u64 %0, t; }" : "=r"(a) : "l"(p));
    return a;
}

// logical k within 16-block -> physical position (pair permutation so that an
// LDS.64 at 4q yields logical pairs {2q,2q+1} and {2q+8,2q+9})
__device__ __forceinline__ int kperm(int w) {
    return 4 * ((w & 7) >> 1) + ((w >> 3) << 1) + (w & 1);
}

// FMA-only sqrt (avoids MUFU throughput wall on 33.5M sqrts)
__device__ __forceinline__ float fast_sqrt(float x) {
    float xh = 0.5f * x;
    float y = __int_as_float(0x5f3759df - (__float_as_int(x) >> 1));
    y = y * (1.5f - xh * y * y);
    y = y * (1.5f - xh * y * y);
    y = y * (1.5f - xh * y * y);
    return x * y;
}

// ---------------------------------------------------------------------------
// Kernel 1: dist rows (fp16, permuted, +1 diag) + degree -> dinv
// R6 version: coalesced strided loads, scalar permuted stores (measured good).
// ---------------------------------------------------------------------------
__global__ void k_dist(const float* __restrict__ inst) {
    int n = blockIdx.x, b = blockIdx.y;
    const float2* xb = (const float2*)(inst + (size_t)b * NN * 2);
    float2 xn = xb[n];
    float sqn = xn.x * xn.x + xn.y * xn.y;
    __half* drow = g_dist + (size_t)(b * NN + n) * NN;
    float acc = 0.f;
    for (int m = threadIdx.x; m < NN; m += 256) {
        float2 xm = xb[m];
        float sqm = xm.x * xm.x + xm.y * xm.y;
        float dot = xn.x * xm.x + xn.y * xm.y;
        float d2 = sqn + sqm - 2.f * dot;
        float d = (d2 > 0.f) ? fast_sqrt(d2) : 0.f;
        acc += d;
        float v = (m == n) ? d + 1.0f : d;   // fold self-loop into A diagonal
        drow[(m & ~15) + kperm(m & 15)] = __float2half_rn(v);
    }
    __shared__ float red[256];
    red[threadIdx.x] = acc;
    __syncthreads();
    for (int s = 128; s > 0; s >>= 1) {
        if (threadIdx.x < s) red[threadIdx.x] += red[threadIdx.x + s];
        __syncthreads();
    }
    if (threadIdx.x == 0)
        g_dinv[b * NN + n] = rsqrtf(1.0f + red[0]);
}

// ---------------------------------------------------------------------------
// Kernel 2: h0 = instance @ Wn^T + bn
// ---------------------------------------------------------------------------
__global__ void k_proj(const float* __restrict__ inst, const float* __restrict__ Wn,
                       const float* __restrict__ bn, float* __restrict__ h) {
    int idx = blockIdx.x * 256 + threadIdx.x;
    int d = idx & (ND - 1);
    int row = idx >> 7;
    float2 x = ((const float2*)inst)[row];
    h[idx] = x.x * Wn[2 * d] + x.y * Wn[2 * d + 1] + bn[d];
}

// ---------------------------------------------------------------------------
// Kernel 3 (fp16 MMA, output-major): zT[b][e][m] = dinv[m] * sum_d Wg[e,d]*h[m,d]
// A = Wg (rows=e), B = h (rows=m); result staged in smem, coalesced copy-out.
// ---------------------------------------------------------------------------
__global__ void __launch_bounds__(256) k_z(const float* __restrict__ h,
                                           const float* __restrict__ Wg) {
    extern __shared__ char smc[];
    uint32_t sbase = smem_u32(smc);
    uint32_t as_ = sbase, bs_ = sbase + 128u * ZROWB;   // A=Wg, B=h
    int t = threadIdx.x, l = t & 31, wid = t >> 5;
    int wm = wid & 1, wn = wid >> 1;
    int row0 = blockIdx.x * 128;
    int b = row0 >> 11;
    int m0g = row0 & (NN - 1);

#pragma unroll
    for (int q = 0; q < 16; q++) {
        int idx = q * 256 + t;
        int r = idx >> 5, u = idx & 31;
        float4 wv = *(const float4*)&Wg[r * ND + 4 * u];
        float4 hv = *(const float4*)&h[(size_t)(row0 + r) * ND + 4 * u];
        int blk = u >> 2;
        int p0 = 2 * (u & 3), p1 = p0 + 1;
        int s0 = (p0 < 4) ? 2 * p0 : 2 * (p0 - 4) + 1;
        int s1 = (p1 < 4) ? 2 * p1 : 2 * (p1 - 4) + 1;
        uint32_t base = (uint32_t)(r * ZROWB + blk * 32);
        *(__half2*)(smc + base + s0 * 4) = __floats2half2_rn(wv.x, wv.y);
        *(__half2*)(smc + base + s1 * 4) = __floats2half2_rn(wv.z, wv.w);
        *(__half2*)(smc + 128u * ZROWB + base + s0 * 4) = __floats2half2_rn(hv.x, hv.y);
        *(__half2*)(smc + 128u * ZROWB + base + s1 * 4) = __floats2half2_rn(hv.z, hv.w);
    }
    __syncthreads();

    float c[4][4][4];
#pragma unroll
    for (int i = 0; i < 4; i++)
#pragma unroll
        for (int j = 0; j < 4; j++)
#pragma unroll
            for (int k = 0; k < 4; k++) c[i][j][k] = 0.f;

#pragma unroll
    for (int s = 0; s < 8; s++) {
        uint32_t bf[4][2];
#pragma unroll
        for (int nt = 0; nt < 4; nt++) {
            int nrow = wn * 32 + nt * 8 + (l >> 2);
            asm volatile("ld.shared.v2.b32 {%0,%1}, [%2];"
                         : "=r"(bf[nt][0]), "=r"(bf[nt][1])
                         : "r"(bs_ + (uint32_t)(nrow * ZROWB + s * 32 + (l & 3) * 8)));
        }
#pragma unroll
        for (int mt = 0; mt < 4; mt++) {
            uint32_t af[4];
            int mrow = wm * 64 + mt * 16 + (l >> 2);
            asm volatile("ld.shared.v2.b32 {%0,%1}, [%2];"
                         : "=r"(af[0]), "=r"(af[2])
                         : "r"(as_ + (uint32_t)(mrow * ZROWB + s * 32 + (l & 3) * 8)));
            asm volatile("ld.shared.v2.b32 {%0,%1}, [%2];"
                         : "=r"(af[1]), "=r"(af[3])
                         : "r"(as_ + (uint32_t)((mrow + 8) * ZROWB + s * 32 + (l & 3) * 8)));
#pragma unroll
            for (int nt = 0; nt < 4; nt++) {
                asm volatile(
                    "mma.sync.aligned.m16n8k16.row.col.f32.f16.f16.f32 "
                    "{%0,%1,%2,%3}, {%4,%5,%6,%7}, {%8,%9}, {%0,%1,%2,%3};"
                    : "+f"(c[mt][nt][0]), "+f"(c[mt][nt][1]),
                      "+f"(c[mt][nt][2]), "+f"(c[mt][nt][3])
                    : "r"(af[0]), "r"(af[1]), "r"(af[2]), "r"(af[3]),
                      "r"(bf[nt][0]), "r"(bf[nt][1]));
            }
        }
    }

    float2 dv[4];
#pragma unroll
    for (int nt = 0; nt < 4; nt++)
        dv[nt] = *(const float2*)&g_dinv[b * NN + m0g + wn * 32 + nt * 8 + 2 * (l & 3)];

    __syncthreads();
#pragma unroll
    for (int mt = 0; mt < 4; mt++) {
        int e0 = wm * 64 + mt * 16 + (l >> 2);
#pragma unroll
        for (int nt = 0; nt < 4; nt++) {
            int mloc = wn * 32 + nt * 8 + 2 * (l & 3);
            int phys = (mloc & ~15) + kperm(mloc & 15);
            *(__half2*)(smc + (uint32_t)(e0 * ZROWB + phys * 2)) =
                __floats2half2_rn(c[mt][nt][0] * dv[nt].x, c[mt][nt][1] * dv[nt].y);
            *(__half2*)(smc + (uint32_t)((e0 + 8) * ZROWB + phys * 2)) =
                __floats2half2_rn(c[mt][nt][2] * dv[nt].x, c[mt][nt][3] * dv[nt].y);
        }
    }
    __syncthreads();

    __half* zTb = g_zT + (size_t)b * ND * NN;
#pragma unroll
    for (int it = 0; it < 8; it++) {
        int idx = it * 256 + t;
        int e = idx >> 4, ch = idx & 15;
        uint4 v = *(const uint4*)(smc + (uint32_t)(e * ZROWB + ch * 16));
        *(uint4*)(zTb + (size_t)e * NN + m0g + ch * 8) = v;
    }
}

// ---------------------------------------------------------------------------
// Kernel 4: fp16 m16n8k16 mma.sync GEMM (R6 mainloop) + fused stats partials.
// h[n,:] = tanh( dinv[n]*((dist+I)[n,:] @ z) + bg ) + h[n,:]
// Epilogue also reduces sum/sumsq over this CTA's 128 rows per d and writes
// g_part[b][tile][d] (deterministic, no atomics).
// ---------------------------------------------------------------------------
__global__ void __launch_bounds__(256) k_gemm_mma(float* __restrict__ h,
                                                  const float* __restrict__ bg_l) {
    extern __shared__ char smc[];
    uint32_t sbase = smem_u32(smc);
    int t = threadIdx.x, l = t & 31, wid = t >> 5;
    int wm = wid & 1, wn = wid >> 1;
    int b = blockIdx.y, n0 = blockIdx.x * 128;
    const __half* Ab = g_dist + ((size_t)b * NN + n0) * NN;
    const __half* Bt = g_zT + (size_t)b * ND * NN;

    float c[4][4][4];
#pragma unroll
    for (int i = 0; i < 4; i++)
#pragma unroll
        for (int j = 0; j < 4; j++)
#pragma unroll
            for (int k = 0; k < 4; k++) c[i][j][k] = 0.f;

#define LOADT(P, K0)                                                             \
    {                                                                            \
        uint32_t xas = sbase + (P) * 40960u;                                     \
        uint32_t xbs = xas + 20480u;                                             \
        _Pragma("unroll")                                                        \
        for (int q = 0; q < 4; q++) {                                            \
            int idx = q * 256 + t;                                               \
            int r_ = idx >> 3;                                                   \
            int c16 = idx & 7;                                                   \
            uint32_t so = (uint32_t)(r_ * ROWB + c16 * 16);                      \
            asm volatile("cp.async.cg.shared.global [%0], [%1], 16;"             \
                         :: "r"(xas + so), "l"(Ab + (size_t)r_ * NN + (K0) + c16 * 8)); \
            asm volatile("cp.async.cg.shared.global [%0], [%1], 16;"             \
                         :: "r"(xbs + so), "l"(Bt + (size_t)r_ * NN + (K0) + c16 * 8)); \
        }                                                                        \
        asm volatile("cp.async.commit_group;");                                  \
    }

#define COMPUTE(P)                                                               \
    {                                                                            \
        uint32_t as_ = sbase + (P) * 40960u;                                     \
        uint32_t bs_ = as_ + 20480u;                                             \
        _Pragma("unroll")                                                        \
        for (int s = 0; s < 4; s++) {                                            \
            uint32_t bf[4][2];                                                   \
            _Pragma("unroll")                                                    \
            for (int nt = 0; nt < 4; nt++) {                                     \
                int nrow = wn * 32 + nt * 8 + (l >> 2);                          \
                asm volatile("ld.shared.v2.b32 {%0,%1}, [%2];"                   \
                             : "=r"(bf[nt][0]), "=r"(bf[nt][1])                  \
                             : "r"(bs_ + (uint32_t)(nrow * ROWB + s * 32 + (l & 3) * 8))); \
            }                                                                    \
            _Pragma("unroll")                                                    \
            for (int mt = 0; mt < 4; mt++) {                                     \
                uint32_t af[4];                                                  \
                int mrow = wm * 64 + mt * 16 + (l >> 2);                         \
                asm volatile("ld.shared.v2.b32 {%0,%1}, [%2];"                   \
                             : "=r"(af[0]), "=r"(af[2])                          \
                             : "r"(as_ + (uint32_t)(mrow * ROWB + s * 32 + (l & 3) * 8))); \
                asm volatile("ld.shared.v2.b32 {%0,%1}, [%2];"                   \
                             : "=r"(af[1]), "=r"(af[3])                          \
                             : "r"(as_ + (uint32_t)((mrow + 8) * ROWB + s * 32 + (l & 3) * 8))); \
                _Pragma("unroll")                                                \
                for (int nt = 0; nt < 4; nt++) {                                 \
                    asm volatile(                                                \
                        "mma.sync.aligned.m16n8k16.row.col.f32.f16.f16.f32 "     \
                        "{%0,%1,%2,%3}, {%4,%5,%6,%7}, {%8,%9}, {%0,%1,%2,%3};"  \
                        : "+f"(c[mt][nt][0]), "+f"(c[mt][nt][1]),                \
                          "+f"(c[mt][nt][2]), "+f"(c[mt][nt][3])                 \
                        : "r"(af[0]), "r"(af[1]), "r"(af[2]), "r"(af[3]),        \
                          "r"(bf[nt][0]), "r"(bf[nt][1]));                       \
                }                                                                \
            }                                                                    \
        }                                                                        \
    }

    LOADT(0, 0);
    LOADT(1, BK);
    int p = 0;
    for (int it = 0; it < NIT; it++) {
        if (it + 1 < NIT)
            asm volatile("cp.async.wait_group 1;");
        else
            asm volatile("cp.async.wait_group 0;");
        __syncthreads();
        if (it + 2 < NIT) {
            int pn = (it + 2) % 3;
            LOADT(pn, (it + 2) * BK);
        }
        COMPUTE(p);
        p = (p + 1) % 3;
    }

    // epilogue: dinv + bias + tanh + residual, accumulating stats partials
    float ssum[8], ssq[8];
#pragma unroll
    for (int j = 0; j < 8; j++) { ssum[j] = 0.f; ssq[j] = 0.f; }
#pragma unroll
    for (int mt = 0; mt < 4; mt++) {
        int r0 = n0 + wm * 64 + mt * 16 + (l >> 2);
        int r1 = r0 + 8;
        float dv0 = g_dinv[b * NN + r0];
        float dv1 = g_dinv[b * NN + r1];
#pragma unroll
        for (int nt = 0; nt < 4; nt++) {
            int cc = wn * 32 + nt * 8 + 2 * (l & 3);
            float bg0 = bg_l[cc], bg1 = bg_l[cc + 1];
            size_t h0o = ((size_t)b * NN + r0) * ND + cc;
            size_t h1o = ((size_t)b * NN + r1) * ND + cc;
            float2 hv0 = *(const float2*)&h[h0o];
            float2 hv1 = *(const float2*)&h[h1o];
            float2 o0, o1;
            o0.x = tanhf(dv0 * c[mt][nt][0] + bg0) + hv0.x;
            o0.y = tanhf(dv0 * c[mt][nt][1] + bg1) + hv0.y;
            o1.x = tanhf(dv1 * c[mt][nt][2] + bg0) + hv1.x;
            o1.y = tanhf(dv1 * c[mt][nt][3] + bg1) + hv1.y;
            *(float2*)&h[h0o] = o0;
            *(float2*)&h[h1o] = o1;
            ssum[2 * nt]     += o0.x + o1.x;
            ssum[2 * nt + 1] += o0.y + o1.y;
            ssq[2 * nt]      += o0.x * o0.x + o1.x * o1.x;
            ssq[2 * nt + 1]  += o0.y * o0.y + o1.y * o1.y;
        }
    }
    // reduce over the 8 lane-row groups (lanes sharing l&3)
#pragma unroll
    for (int off = 4; off < 32; off <<= 1)
#pragma unroll
        for (int j = 0; j < 8; j++) {
            ssum[j] += __shfl_xor_sync(0xffffffffu, ssum[j], off);
            ssq[j]  += __shfl_xor_sync(0xffffffffu, ssq[j], off);
        }
    __syncthreads();           // done with mainloop smem; reuse for cross-warp stats
    float* sp = (float*)smc;   // [0:256) sums (wm-major), [256:512) sumsqs
    if ((l >> 2) == 0) {
#pragma unroll
        for (int j = 0; j < 8; j++) {
            int col = wn * 32 + (j >> 1) * 8 + 2 * (l & 3) + (j & 1);
            sp[wm * 128 + col] = ssum[j];
            sp[256 + wm * 128 + col] = ssq[j];
        }
    }
    __syncthreads();
    if (t < 128) {
        float s = sp[t] + sp[128 + t];
        float q = sp[256 + t] + sp[384 + t];
        g_part[((size_t)b * 16 + blockIdx.x) * ND + t] = make_float2(s, q);
    }
#undef LOADT
#undef COMPUTE
}

// ---------------------------------------------------------------------------
// Kernel 5: finalize GraphNorm stats from 16 per-tile partials
// ---------------------------------------------------------------------------
__global__ void k_fin(const float* __restrict__ gna) {
    int b = blockIdx.x, d = threadIdx.x;
    float s = 0.f, q = 0.f;
#pragma unroll
    for (int tile = 0; tile < 16; tile++) {
        float2 v = g_part[((size_t)b * 16 + tile) * ND + d];
        s += v.x; q += v.y;
    }
    float mean = s * (1.f / NN);
    float eh2 = q * (1.f / NN);
    float a = gna[d];
    float var = eh2 - (2.f * a - a * a) * mean * mean;
    g_mean[b * ND + d] = mean;
    g_rstd[b * ND + d] = rsqrtf(var + 1e-5f);
}

// ---------------------------------------------------------------------------
// Kernel 6: normalize in place
// ---------------------------------------------------------------------------
__global__ void k_norm(float* __restrict__ h, const float* __restrict__ gnw,
                       const float* __restrict__ gnb, const float* __restrict__ gna) {
    int idx = blockIdx.x * 256 + threadIdx.x;
    int d = idx & (ND - 1);
    int b = idx >> 18;
    float m = g_mean[b * ND + d];
    float rs = g_rstd[b * ND + d];
    float v = h[idx];
    h[idx] = gnw[d] * (v - gna[d] * m) * rs + gnb[d];
}

// ---------------------------------------------------------------------------
extern "C" void kernel_launch(void* const* d_in, const int* in_sizes, int n_in,
                              void* d_out, int out_size) {
    const float* inst = (const float*)d_in[0];
    const float* Wn   = (const float*)d_in[1];
    const float* bn   = (const float*)d_in[2];
    const float* Wg   = (const float*)d_in[3];
    const float* bg   = (const float*)d_in[4];
    const float* gnw  = (const float*)d_in[5];
    const float* gnb  = (const float*)d_in[6];
    const float* gna  = (const float*)d_in[7];
    float* h = (float*)d_out;

    const int SMEM_GEMM = 3 * 40960;             // 3 stages x (A 20KB + B 20KB)
    const int SMEM_Z    = 2 * 128 * (int)ZROWB;  // 72 KB
    static int smem_set = 0;
    if (!smem_set) {
        cudaFuncSetAttribute(k_gemm_mma, cudaFuncAttributeMaxDynamicSharedMemorySize, SMEM_GEMM);
        cudaFuncSetAttribute(k_z, cudaFuncAttributeMaxDynamicSharedMemorySize, SMEM_Z);
        smem_set = 1;
    }

    k_dist<<<dim3(NN, NB), 256>>>(inst);
    k_proj<<<(NB * NN * ND) / 256, 256>>>(inst, Wn, bn, h);
    for (int l = 0; l < 3; l++) {
        k_z<<<NB * NN / 128, 256, SMEM_Z>>>(h, Wg + l * ND * ND);
        k_gemm_mma<<<dim3(NN / 128, NB), 256, SMEM_GEMM>>>(h, bg + l * ND);
        k_fin<<<NB, ND>>>(gna);
        k_norm<<<(NB * NN * ND) / 256, 256>>>(h, gnw, gnb, gna);
    }
}